// round 4
// baseline (speedup 1.0000x reference)
#include <cuda_runtime.h>
#include <cuda_bf16.h>

// Single fused persistent kernel.
// Closed-form: per_pair = cos^2(1-cos^2) = (1 - cos(4*dTheta))/8.
// Per node v with m unit slots, C = sum cos4t, S = sum sin4t:
//   sum over unit-slot pairs = (m^2 - C^2 - S^2)/16
// Denominator P = sum_v n(n-1)/2 over ALL slots (zero-length slots count in n,
// contribute 0 to numerator). loss = sum_v(...) / (16*P).
//
// Phase 1 (edges) -> software grid barrier (single wave, 2 CTAs/SM) ->
// Phase 2 (node reduce + finalize). All state self-cleaning for graph replay.

#define NB 296          // 2 CTAs per SM on 148 SMs -> guaranteed co-resident
#define NT 256
#define MAXN 65536

__device__ float4 g_CSW[MAXN];          // {C, S, W(unit cnt), Z(zero cnt)}
__device__ double g_num;
__device__ double g_pairs;
__device__ unsigned g_count;            // barrier arrival
__device__ volatile unsigned g_release; // barrier release flag
__device__ unsigned g_done;             // finalize counter

__device__ __forceinline__ void red_v4(float4* addr, float a, float b, float c, float d) {
    asm volatile("red.global.add.v4.f32 [%0], {%1, %2, %3, %4};"
                 :: "l"(addr), "f"(a), "f"(b), "f"(c), "f"(d) : "memory");
}

__device__ __forceinline__ void do_edge(const float2* __restrict__ pos, int a, int b) {
    float2 pa = __ldg(pos + a);
    float2 pb = __ldg(pos + b);
    float dx = pb.x - pa.x;
    float dy = pb.y - pa.y;
    float n2 = dx * dx + dy * dy;
    float c4, s4, w, z;
    if (n2 > 0.f) {
        float inv = rsqrtf(n2);
        float c = dx * inv, s = dy * inv;
        float c2 = c * c - s * s;
        float s2 = 2.f * c * s;
        c4 = c2 * c2 - s2 * s2;
        s4 = 2.f * c2 * s2;
        w = 1.f; z = 0.f;
    } else {
        c4 = 0.f; s4 = 0.f; w = 0.f; z = 1.f;
    }
    red_v4(&g_CSW[a], c4, s4, w, z);
    red_v4(&g_CSW[b], c4, s4, w, z);
}

__global__ void __launch_bounds__(NT)
fused_kernel(const float2* __restrict__ pos,
             const int* __restrict__ src,
             const int* __restrict__ dst,
             int E, int N, float* __restrict__ out) {
    const int tid = blockIdx.x * NT + threadIdx.x;
    const int nthreads = NB * NT;

    // ---- Phase 1: edges, 8 per thread via int4 loads ----
    for (int base = tid * 8; base < E; base += nthreads * 8) {
        if (base + 8 <= E) {
            int4 s0 = *(const int4*)(src + base);
            int4 s1 = *(const int4*)(src + base + 4);
            int4 d0 = *(const int4*)(dst + base);
            int4 d1 = *(const int4*)(dst + base + 4);
            do_edge(pos, s0.x, d0.x);
            do_edge(pos, s0.y, d0.y);
            do_edge(pos, s0.z, d0.z);
            do_edge(pos, s0.w, d0.w);
            do_edge(pos, s1.x, d1.x);
            do_edge(pos, s1.y, d1.y);
            do_edge(pos, s1.z, d1.z);
            do_edge(pos, s1.w, d1.w);
        } else {
            for (int e = base; e < E; e++) do_edge(pos, src[e], dst[e]);
        }
    }

    // ---- Grid barrier (all NB blocks co-resident: single wave) ----
    __syncthreads();
    if (threadIdx.x == 0) {
        __threadfence();
        if (atomicAdd(&g_count, 1u) == (unsigned)(gridDim.x - 1)) {
            g_count = 0u;
            __threadfence();
            g_release = 1u;
        } else {
            while (g_release == 0u) { __nanosleep(64); }
        }
        __threadfence();   // acquire: phase-1 reductions now visible
    }
    __syncthreads();

    // ---- Phase 2: per-node closed form + self-clean ----
    double num = 0.0, p = 0.0;
    for (int i = tid; i < N; i += nthreads) {
        float4 v = g_CSW[i];
        g_CSW[i] = make_float4(0.f, 0.f, 0.f, 0.f);
        num += (double)v.z * (double)v.z
             - (double)v.x * (double)v.x
             - (double)v.y * (double)v.y;
        double nn = (double)(v.z + v.w);
        p += 0.5 * nn * (nn - 1.0);
    }

    // ---- Block reduce ----
    #pragma unroll
    for (int off = 16; off > 0; off >>= 1) {
        num += __shfl_down_sync(0xffffffffu, num, off);
        p   += __shfl_down_sync(0xffffffffu, p, off);
    }
    __shared__ double sh_num[8];
    __shared__ double sh_p[8];
    int lane = threadIdx.x & 31;
    int wid  = threadIdx.x >> 5;
    if (lane == 0) { sh_num[wid] = num; sh_p[wid] = p; }
    __syncthreads();
    if (wid == 0) {
        num = (lane < 8) ? sh_num[lane] : 0.0;
        p   = (lane < 8) ? sh_p[lane]   : 0.0;
        #pragma unroll
        for (int off = 4; off > 0; off >>= 1) {
            num += __shfl_down_sync(0xffffffffu, num, off);
            p   += __shfl_down_sync(0xffffffffu, p, off);
        }
        if (lane == 0 && (num != 0.0 || p != 0.0)) {
            atomicAdd(&g_num, num);
            atomicAdd(&g_pairs, p);
        }
    }
    __syncthreads();

    // ---- Finalize (last block) ----
    if (threadIdx.x == 0) {
        __threadfence();
        if (atomicAdd(&g_done, 1u) == (unsigned)(gridDim.x - 1)) {
            double total_num   = atomicAdd(&g_num, 0.0);    // strong L2 reads
            double total_pairs = atomicAdd(&g_pairs, 0.0);
            double denom = 16.0 * total_pairs;
            out[0] = (denom > 0.0) ? (float)(total_num / denom) : 0.0f;
            // reset all state for next graph replay
            g_num = 0.0;
            g_pairs = 0.0;
            g_done = 0u;
            g_release = 0u;
            __threadfence();
        }
    }
}

extern "C" void kernel_launch(void* const* d_in, const int* in_sizes, int n_in,
                              void* d_out, int out_size) {
    const float* pos = (const float*)d_in[0];       // (1, N, 2)
    const int* edge_index = (const int*)d_in[2];    // (2, E)
    int N = in_sizes[0] / 2;
    int E = in_sizes[2] / 2;
    const int* src = edge_index;
    const int* dst = edge_index + E;
    float* out = (float*)d_out;

    fused_kernel<<<NB, NT>>>((const float2*)pos, src, dst, E, N, out);
}